// round 7
// baseline (speedup 1.0000x reference)
#include <cuda_runtime.h>
#include <cstdint>

// Problem constants
#define B    256
#define T    2000
#define H    256
#define NIN  64
#define NT   8
#define DIN  72   // NIN + NT
#define O    32

typedef unsigned long long u64;

// ---------- packed f32x2 helpers (sm_100+) ----------
__device__ __forceinline__ u64 ffma2(u64 a, u64 b, u64 c) {
    u64 d;
    asm("fma.rn.f32x2 %0, %1, %2, %3;" : "=l"(d) : "l"(a), "l"(b), "l"(c));
    return d;
}
__device__ __forceinline__ float2 unpk(u64 v) {
    float2 r;
    asm("mov.b64 {%0, %1}, %2;" : "=f"(r.x), "=f"(r.y) : "l"(v));
    return r;
}

// ---------- scratch (device globals: allocation-free) ----------
__device__ float g_inp[(size_t)T * B * H];             // [t][b][h] 524 MB
__device__ float g_hh [(size_t)T * B * H];             // [t][b][h] 524 MB

// =====================================================================
// P1: g_inp[t][b][h] = dot(W_in[h][0:64], x[b][t][:])
//                    + b_in[h] + dot(W_in[h][64:72], task[b][:])
// One block per (b, t-tile of 50). W_in row (64 f) lives in registers;
// the task-id part of the projection is recomputed per block (8 FMAs).
// =====================================================================
#define TT 50
__global__ void __launch_bounds__(256) inproj_kernel(const float* __restrict__ x,
                                                     const float* __restrict__ task,
                                                     const float* __restrict__ Win,
                                                     const float* __restrict__ bin) {
    int b  = blockIdx.x;
    int t0 = blockIdx.y * TT;
    int h  = threadIdx.x;

    __shared__ float xs[TT * NIN];   // 12.8 KB, contiguous in gmem
    __shared__ float ts[NT];

    if (h < NT) ts[h] = task[b * NT + h];

    // W_in[h][0:64] packed into 32 f32x2 regs (row base h*288 B, 16B aligned)
    u64 w[32];
    {
        const float4* wr = (const float4*)(Win + (size_t)h * DIN);
        #pragma unroll
        for (int i = 0; i < 16; i++) {
            float4 v = wr[i];
            asm("mov.b64 %0, {%1, %2};" : "=l"(w[2*i])   : "f"(v.x), "f"(v.y));
            asm("mov.b64 %0, {%1, %2};" : "=l"(w[2*i+1]) : "f"(v.z), "f"(v.w));
        }
    }

    // cooperative load of x tile: contiguous TT*64 floats
    {
        const float4* xg = (const float4*)(x + ((size_t)b * T + t0) * NIN);
        float4* xsv = (float4*)xs;
        for (int i = h; i < TT * NIN / 4; i += 256) xsv[i] = xg[i];
    }
    __syncthreads();

    // per-(b,h) task projection: b_in[h] + 8 FMAs (same FMA order every block)
    float tp = bin[h];
    #pragma unroll
    for (int j = 0; j < NT; j++) tp = fmaf(Win[h * DIN + NIN + j], ts[j], tp);

    for (int tt = 0; tt < TT; tt++) {
        const ulonglong2* xp = (const ulonglong2*)&xs[tt * NIN];
        u64 a0 = 0, a1 = 0;
        #pragma unroll
        for (int i = 0; i < 16; i++) {
            ulonglong2 v = xp[i];
            a0 = ffma2(w[2*i],   v.x, a0);
            a1 = ffma2(w[2*i+1], v.y, a1);
        }
        float2 f0 = unpk(a0), f1 = unpk(a1);
        // streaming store: single-use 524 MB buffer, keep it out of L2's way
        __stcs(&g_inp[((size_t)(t0 + tt) * B + b) * H + h],
               f0.x + f0.y + f1.x + f1.y + tp);
    }
}

// =====================================================================
// P2: the scan. 64 clusters x 2 CTAs. Cluster c -> batch rows [4c, 4c+4).
// CTA rank r owns output rows [128r, 128r+128); its half of W_hh (128 KB)
// lives in registers (thread = (row, k-half), 64 b64 weight regs).
//
// Symmetric epilogue: k-half kh owns batch pair (2kh, 2kh+1). Each half
// writes the partial sums of the pair it does NOT own to red[kh^1][row],
// reads red[kh][row], updates its two h states, stores h history, and
// publishes relu(h) locally + to the peer CTA via st.shared::cluster.
//
// Synchronization (audited): ONE __syncthreads per step (cross-half red
// exchange) + ONE split cluster barrier. The epilogue->next-step ordering
// (relu_s writes, red anti-dependence) is carried by the cluster arrive
// (release) / wait (acquire) pair; every smem load's value is consumed by
// stores preceding the arrive, so no in-flight-load hazard exists.
// g_inp prefetch LDGs are issued BEFORE the cluster wait so memory
// latency overlaps the barrier wait.
// =====================================================================
__global__ void __launch_bounds__(256, 1) __cluster_dims__(2, 1, 1)
scan_kernel(const float* __restrict__ Whh, const float* __restrict__ bhh) {
    int tid = threadIdx.x;
    int row = tid & 127;
    int kh  = tid >> 7;                 // 0: k in [0,128), 1: k in [128,256)
    unsigned rank;
    asm("mov.u32 %0, %%cluster_ctarank;" : "=r"(rank));
    int b0   = (blockIdx.x >> 1) * 4;
    int grow = (int)rank * 128 + row;   // global output row (== my relu k-index)
    int bb0  = kh * 2;                  // first batch this thread owns

    __shared__ float  relu_s[2][4][H];  // [buf][batch][k]  8 KB
    __shared__ float2 red[2][128];      // [pair][row] cross-half partials 2 KB

    // weight half-row in registers: W_hh[grow][kh*128 .. +128)
    ulonglong2 w[32];
    {
        const ulonglong2* wp = (const ulonglong2*)(Whh + (size_t)grow * H + kh * 128);
        #pragma unroll
        for (int i = 0; i < 32; i++) w[i] = wp[i];
    }
    float bh = bhh[grow];

    // zero relu buffer 0 (h0 = 0 -> relu = 0)
    for (int i = tid; i < 4 * H; i += 256) ((float*)relu_s[0])[i] = 0.0f;

    // persistent h state and input-proj regs for the two owned batches
    float hA = 0.f, hB = 0.f;
    float iA, iB;
    {
        size_t base = ((size_t)b0 + bb0) * H + grow;   // t = 0
        iA = __ldcs(&g_inp[base]);
        iB = __ldcs(&g_inp[base + H]);
    }
    __syncthreads();
    asm volatile("barrier.cluster.arrive.aligned;" ::: "memory");
    asm volatile("barrier.cluster.wait.aligned;"   ::: "memory");

    // peer DSMEM base for relu_s (offsets added per store)
    unsigned my_smem = (unsigned)__cvta_generic_to_shared(&relu_s[0][0][0]);
    unsigned peer_base;
    asm("mapa.shared::cluster.u32 %0, %1, %2;" : "=r"(peer_base) : "r"(my_smem), "r"(rank ^ 1u));

    for (int t = 0; t < T; t++) {
        // prefetch next step's input projection BEFORE the barrier wait:
        // LDG latency overlaps both the wait and the FMA loop.
        float nA = 0.f, nB = 0.f;
        if (t + 1 < T) {
            size_t base = ((size_t)(t + 1) * B + b0 + bb0) * H + grow;
            nA = __ldcs(&g_inp[base]);
            nB = __ldcs(&g_inp[base + H]);
        }

        if (t) asm volatile("barrier.cluster.wait.aligned;" ::: "memory");
        int cur = t & 1;

        const ulonglong2* r0 = (const ulonglong2*)&relu_s[cur][0][kh * 128];
        const ulonglong2* r1 = (const ulonglong2*)&relu_s[cur][1][kh * 128];
        const ulonglong2* r2 = (const ulonglong2*)&relu_s[cur][2][kh * 128];
        const ulonglong2* r3 = (const ulonglong2*)&relu_s[cur][3][kh * 128];

        u64 a0 = 0, a1 = 0, a2 = 0, a3 = 0;
        #pragma unroll
        for (int i = 0; i < 32; i++) {
            ulonglong2 wv = w[i];
            ulonglong2 v0 = r0[i], v1 = r1[i], v2 = r2[i], v3 = r3[i];
            a0 = ffma2(wv.x, v0.x, a0);
            a1 = ffma2(wv.x, v1.x, a1);
            a2 = ffma2(wv.x, v2.x, a2);
            a3 = ffma2(wv.x, v3.x, a3);
            a0 = ffma2(wv.y, v0.y, a0);
            a1 = ffma2(wv.y, v1.y, a1);
            a2 = ffma2(wv.y, v2.y, a2);
            a3 = ffma2(wv.y, v3.y, a3);
        }
        float2 f0 = unpk(a0), f1 = unpk(a1), f2 = unpk(a2), f3 = unpk(a3);
        float s0 = f0.x + f0.y, s1 = f1.x + f1.y, s2 = f2.x + f2.y, s3 = f3.x + f3.y;

        // own-pair sums / other-pair sums
        float ownX = kh ? s2 : s0;
        float ownY = kh ? s3 : s1;
        float othX = kh ? s0 : s2;
        float othY = kh ? s1 : s3;

        red[kh ^ 1][row] = make_float2(othX, othY);
        __syncthreads();                       // cross-half red exchange (only CTA barrier per step)

        {
            float2 p = red[kh][row];
            float rcA = ownX + p.x + iA + bh;
            float rcB = ownY + p.y + iB + bh;
            hA = 0.9f * hA + 0.1f * rcA;
            hB = 0.9f * hB + 0.1f * rcB;

            // h history for the deferred output GEMM (single-use: streaming store)
            size_t hb = ((size_t)t * B + b0 + bb0) * H + grow;
            __stcs(&g_hh[hb],     hA);
            __stcs(&g_hh[hb + H], hB);

            int nxt = cur ^ 1;
            float eA = fmaxf(hA, 0.f), eB = fmaxf(hB, 0.f);
            // local copy (own k-half of the next-step activation tile)
            relu_s[nxt][bb0][grow]     = eA;
            relu_s[nxt][bb0 + 1][grow] = eB;
            // peer copy via DSMEM
            unsigned off = (unsigned)((((nxt * 4 + bb0) * H) + grow) * 4);
            asm volatile("st.shared::cluster.b32 [%0], %1;" :: "r"(peer_base + off),         "r"(__float_as_uint(eA)));
            asm volatile("st.shared::cluster.b32 [%0], %1;" :: "r"(peer_base + off + H * 4), "r"(__float_as_uint(eB)));

            iA = nA; iB = nB;
        }
        // release: publishes relu_s / DSMEM stores for every next-step reader.
        // Next step's cluster wait (acquire) provides the matching ordering,
        // intra-CTA included — no trailing __syncthreads needed.
        asm volatile("barrier.cluster.arrive.aligned;" ::: "memory");
    }
    asm volatile("barrier.cluster.wait.aligned;" ::: "memory");        // balance phases before exit
}

// =====================================================================
// P3: out[b][t][o] = h_hist[t][b][:] . W_out[o][:] + b_out[o]
// One block per t. thread = (ksec = tid>>5, o = tid&31); 32 rounds of
// 8 batch rows; k-split partials reduced through smem.
// =====================================================================
__global__ void __launch_bounds__(256) out_kernel(const float* __restrict__ Wout,
                                                  const float* __restrict__ bout,
                                                  float* __restrict__ out) {
    int t   = blockIdx.x;
    int tid = threadIdx.x;
    int o   = tid & 31;
    int ks  = tid >> 5;                 // k-section 0..7 (32 k each)

    __shared__ float hs[8][H];          // 8 batch rows  (8 KB)
    __shared__ float red[8][8][O];      // [ksec][bb][o] (8 KB)

    // W_out[o][ks*32 .. +32) in registers (16 f32x2)
    u64 w[16];
    {
        const ulonglong2* wp = (const ulonglong2*)(Wout + (size_t)o * H + ks * 32);
        #pragma unroll
        for (int i = 0; i < 8; i++) { ulonglong2 v = wp[i]; w[2*i] = v.x; w[2*i+1] = v.y; }
    }
    float bo = bout[o];

    const float4* hg = (const float4*)(g_hh + (size_t)t * B * H);
    float4 p0 = __ldcs(&hg[tid]), p1 = __ldcs(&hg[tid + 256]);  // prefetch round 0

    for (int r = 0; r < 32; r++) {
        ((float4*)hs)[tid]       = p0;
        ((float4*)hs)[tid + 256] = p1;
        if (r + 1 < 32) {                        // prefetch next round (streaming)
            p0 = __ldcs(&hg[(r + 1) * 512 + tid]);
            p1 = __ldcs(&hg[(r + 1) * 512 + 256 + tid]);
        }
        __syncthreads();

        #pragma unroll
        for (int bb = 0; bb < 8; bb++) {
            const u64* hp = (const u64*)&hs[bb][ks * 32];
            u64 a0 = 0, a1 = 0;
            #pragma unroll
            for (int i = 0; i < 8; i++) {
                a0 = ffma2(w[2*i],   hp[2*i],   a0);
                a1 = ffma2(w[2*i+1], hp[2*i+1], a1);
            }
            float2 fa = unpk(a0), fb = unpk(a1);
            red[ks][bb][o] = fa.x + fa.y + fb.x + fb.y;
        }
        __syncthreads();

        {   // reduce 8 k-sections; thread -> (bb = tid>>5, o = tid&31)
            int bb = tid >> 5;
            float s = bo;
            #pragma unroll
            for (int k = 0; k < 8; k++) s += red[k][bb][o];
            int b = r * 8 + bb;
            out[((size_t)b * T + t) * O + o] = s;
        }
        __syncthreads();
    }
}

// =====================================================================
extern "C" void kernel_launch(void* const* d_in, const int* in_sizes, int n_in,
                              void* d_out, int out_size) {
    const float* x    = (const float*)d_in[0];
    const float* task = (const float*)d_in[1];
    const float* Win  = (const float*)d_in[2];
    const float* bin  = (const float*)d_in[3];
    const float* Whh  = (const float*)d_in[4];
    const float* bhh  = (const float*)d_in[5];
    const float* Wout = (const float*)d_in[6];
    const float* bout = (const float*)d_in[7];
    float* out = (float*)d_out;

    inproj_kernel<<<dim3(B, T / TT), 256>>>(x, task, Win, bin);
    scan_kernel<<<128, 256>>>(Whh, bhh);
    out_kernel<<<T, 256>>>(Wout, bout, out);
}

// round 10
// speedup vs baseline: 1.1634x; 1.1634x over previous
#include <cuda_runtime.h>
#include <cstdint>

// Problem constants
#define B    256
#define T    2000
#define H    256
#define NIN  64
#define NT   8
#define DIN  72   // NIN + NT
#define O    32

typedef unsigned long long u64;

// ---------- packed f32x2 helpers (sm_100+) ----------
__device__ __forceinline__ u64 ffma2(u64 a, u64 b, u64 c) {
    u64 d;
    asm("fma.rn.f32x2 %0, %1, %2, %3;" : "=l"(d) : "l"(a), "l"(b), "l"(c));
    return d;
}
__device__ __forceinline__ float2 unpk(u64 v) {
    float2 r;
    asm("mov.b64 {%0, %1}, %2;" : "=f"(r.x), "=f"(r.y) : "l"(v));
    return r;
}

// mbarrier try_wait (parity). CLUSTER-scope acquire: half of each buffer's
// transactions are peer-CTA st.async writes; .cta acquire would not make
// that DSMEM data visible.
__device__ __forceinline__ void mbar_wait(unsigned mb, unsigned phase) {
    unsigned done;
    asm volatile(
        "{\n\t.reg .pred p;\n\t"
        "mbarrier.try_wait.parity.acquire.cluster.shared::cta.b64 p, [%1], %2;\n\t"
        "selp.b32 %0, 1, 0, p;\n\t}"
        : "=r"(done) : "r"(mb), "r"(phase) : "memory");
    if (!done) {
        asm volatile(
            "{\n\t.reg .pred P1;\n\t"
            "WL%=:\n\t"
            "mbarrier.try_wait.parity.acquire.cluster.shared::cta.b64 P1, [%0], %1, 0x989680;\n\t"
            "@P1 bra.uni WD%=;\n\t"
            "bra.uni WL%=;\n\t"
            "WD%=:\n\t}"
            :: "r"(mb), "r"(phase) : "memory");
    }
}

#define MBAR_INIT(mb, cnt) \
    asm volatile("mbarrier.init.shared.b64 [%0], %1;" :: "r"(mb), "r"(cnt) : "memory")
#define MBAR_ARM(mb, tx) \
    asm volatile("mbarrier.arrive.expect_tx.shared.b64 _, [%0], %1;" :: "r"(mb), "r"(tx) : "memory")
#define ST_ASYNC_B32(daddr, val, mbaddr) \
    asm volatile("st.async.shared::cluster.mbarrier::complete_tx::bytes.b32 [%0], %1, [%2];" \
                 :: "r"(daddr), "r"(__float_as_uint(val)), "r"(mbaddr) : "memory")

// ---------- scratch (device globals: allocation-free) ----------
__device__ float g_inp[(size_t)T * B * H];             // [t][b][h] 524 MB
__device__ float g_hh [(size_t)T * B * H];             // [t][b][h] 524 MB

// =====================================================================
// P1: g_inp[t][b][h] = dot(W_in[h][0:64], x[b][t][:])
//                    + b_in[h] + dot(W_in[h][64:72], task[b][:])
// One block per (b, t-tile of 50). W_in row (64 f) in registers.
// 2 timesteps per inner iteration (4 accumulator chains) for ILP.
// __launch_bounds__(256, 2): cap regs at 128 so the ILP bump cannot
// drop occupancy to 1 CTA/SM (measured baseline ran 2 CTAs @ 94 regs).
// =====================================================================
#define TT 50
__global__ void __launch_bounds__(256, 2) inproj_kernel(const float* __restrict__ x,
                                                        const float* __restrict__ task,
                                                        const float* __restrict__ Win,
                                                        const float* __restrict__ bin) {
    int b  = blockIdx.x;
    int t0 = blockIdx.y * TT;
    int h  = threadIdx.x;

    __shared__ float xs[TT * NIN];   // 12.8 KB, contiguous in gmem
    __shared__ float ts[NT];

    if (h < NT) ts[h] = task[b * NT + h];

    // W_in[h][0:64] packed into 32 f32x2 regs (row base h*288 B, 16B aligned)
    u64 w[32];
    {
        const float4* wr = (const float4*)(Win + (size_t)h * DIN);
        #pragma unroll
        for (int i = 0; i < 16; i++) {
            float4 v = wr[i];
            asm("mov.b64 %0, {%1, %2};" : "=l"(w[2*i])   : "f"(v.x), "f"(v.y));
            asm("mov.b64 %0, {%1, %2};" : "=l"(w[2*i+1]) : "f"(v.z), "f"(v.w));
        }
    }

    // cooperative load of x tile: contiguous TT*64 floats
    {
        const float4* xg = (const float4*)(x + ((size_t)b * T + t0) * NIN);
        float4* xsv = (float4*)xs;
        for (int i = h; i < TT * NIN / 4; i += 256) xsv[i] = xg[i];
    }
    __syncthreads();

    // per-(b,h) task projection: b_in[h] + 8 FMAs (same FMA order every block)
    float tp = bin[h];
    #pragma unroll
    for (int j = 0; j < NT; j++) tp = fmaf(Win[h * DIN + NIN + j], ts[j], tp);

    for (int tt = 0; tt < TT; tt += 2) {
        const ulonglong2* xp = (const ulonglong2*)&xs[tt * NIN];
        const ulonglong2* xq = (const ulonglong2*)&xs[(tt + 1) * NIN];
        u64 a0 = 0, a1 = 0, c0 = 0, c1 = 0;
        #pragma unroll
        for (int i = 0; i < 16; i++) {
            ulonglong2 v = xp[i], q = xq[i];
            a0 = ffma2(w[2*i],   v.x, a0);
            a1 = ffma2(w[2*i+1], v.y, a1);
            c0 = ffma2(w[2*i],   q.x, c0);
            c1 = ffma2(w[2*i+1], q.y, c1);
        }
        float2 f0 = unpk(a0), f1 = unpk(a1), g0 = unpk(c0), g1 = unpk(c1);
        __stcs(&g_inp[((size_t)(t0 + tt) * B + b) * H + h],
               f0.x + f0.y + f1.x + f1.y + tp);
        __stcs(&g_inp[((size_t)(t0 + tt + 1) * B + b) * H + h],
               g0.x + g0.y + g1.x + g1.y + tp);
    }
}

// =====================================================================
// P2: the scan. 64 clusters x 2 CTAs. Cluster c -> batch rows [4c, 4c+4).
// CTA rank r owns output rows [128r, 128r+128); its half of W_hh (128 KB)
// lives in registers. k-half kh owns batch pair (2kh, 2kh+1).
//
// Per-step sync: relu(h) published via st.async with mbarrier complete_tx
// transaction tracking — 2 stores to own CTA + 2 to peer per thread,
// against per-buffer mbarriers armed with expect_tx = 4096 B (2 KB local
// + 2 KB remote). Consumer: try_wait.parity.ACQUIRE.CLUSTER (~60-90 cyc)
// instead of barrier.cluster.wait (~490 cyc + per-step L1 flush).
//
// Ordering (audited twice): buffer-full requires all 512 threads' step-t
// transactions; each thread's publication data-depends on the whole CTA's
// step-t buffer reads (via red + __syncthreads) — so refills happen-after
// all reads. tid0's re-arm precedes any complete_tx of its phase via the
// peer's acquire-wait. Last step publishes nothing -> clean exit.
// =====================================================================
__global__ void __launch_bounds__(256, 1) __cluster_dims__(2, 1, 1)
scan_kernel(const float* __restrict__ Whh, const float* __restrict__ bhh) {
    int tid = threadIdx.x;
    int row = tid & 127;
    int kh  = tid >> 7;                 // 0: k in [0,128), 1: k in [128,256)
    unsigned rank;
    asm("mov.u32 %0, %%cluster_ctarank;" : "=r"(rank));
    int b0   = (blockIdx.x >> 1) * 4;
    int grow = (int)rank * 128 + row;   // global output row (== my relu k-index)
    int bb0  = kh * 2;                  // first batch this thread owns

    __shared__ float  relu_s[2][4][H];  // [buf][batch][k]  8 KB
    __shared__ float2 red[2][128];      // [pair][row] cross-half partials 2 KB
    __shared__ __align__(8) u64 mbar_s[2];  // one mbarrier per relu buffer

    // weight half-row in registers: W_hh[grow][kh*128 .. +128)
    ulonglong2 w[32];
    {
        const ulonglong2* wp = (const ulonglong2*)(Whh + (size_t)grow * H + kh * 128);
        #pragma unroll
        for (int i = 0; i < 32; i++) w[i] = wp[i];
    }
    float bh = bhh[grow];

    unsigned mb_local = (unsigned)__cvta_generic_to_shared(&mbar_s[0]);
    unsigned relu_cta = (unsigned)__cvta_generic_to_shared(&relu_s[0][0][0]);

    if (tid == 0) {
        MBAR_INIT(mb_local,     1u);
        MBAR_INIT(mb_local + 8, 1u);
        MBAR_ARM(mb_local,     4096u);   // buffer 0's first async fill (during t=1)
        MBAR_ARM(mb_local + 8, 4096u);   // buffer 1's first fill (during t=0)
    }
    // zero relu buffer 0 (h0 = 0 -> relu = 0)
    for (int i = tid; i < 4 * H; i += 256) ((float*)relu_s[0])[i] = 0.0f;

    // persistent h state and input-proj regs for the two owned batches
    float hA = 0.f, hB = 0.f;
    float iA, iB;
    {
        size_t base = ((size_t)b0 + bb0) * H + grow;   // t = 0
        iA = __ldcs(&g_inp[base]);
        iB = __ldcs(&g_inp[base + H]);
    }
    __syncthreads();
    // cluster sync once: mbarrier init must be visible before any peer st.async
    asm volatile("barrier.cluster.arrive.aligned;" ::: "memory");
    asm volatile("barrier.cluster.wait.aligned;"   ::: "memory");

    // cluster-window addresses for own and peer relu/mbar
    unsigned own_relu, peer_relu, own_mb, peer_mb;
    asm("mapa.shared::cluster.u32 %0, %1, %2;" : "=r"(own_relu)  : "r"(relu_cta), "r"(rank));
    asm("mapa.shared::cluster.u32 %0, %1, %2;" : "=r"(peer_relu) : "r"(relu_cta), "r"(rank ^ 1u));
    asm("mapa.shared::cluster.u32 %0, %1, %2;" : "=r"(own_mb)    : "r"(mb_local), "r"(rank));
    asm("mapa.shared::cluster.u32 %0, %1, %2;" : "=r"(peer_mb)   : "r"(mb_local), "r"(rank ^ 1u));

    unsigned phases = 0;   // bit j = parity for mbar[j]'s next wait

    for (int t = 0; t < T; t++) {
        int cur = t & 1;

        // prefetch next step's input projection BEFORE the wait:
        // LDG latency overlaps the wait and the FMA loop.
        float nA = 0.f, nB = 0.f;
        if (t + 1 < T) {
            size_t base = ((size_t)(t + 1) * B + b0 + bb0) * H + grow;
            nA = __ldcs(&g_inp[base]);
            nB = __ldcs(&g_inp[base + H]);
        }

        if (t) {
            unsigned mb = mb_local + (unsigned)(cur << 3);
            mbar_wait(mb, (phases >> cur) & 1u);
            phases ^= (1u << cur);
            if (tid == 0) MBAR_ARM(mb, 4096u);   // re-arm for fill at step t+1
        }

        const ulonglong2* r0 = (const ulonglong2*)&relu_s[cur][0][kh * 128];
        const ulonglong2* r1 = (const ulonglong2*)&relu_s[cur][1][kh * 128];
        const ulonglong2* r2 = (const ulonglong2*)&relu_s[cur][2][kh * 128];
        const ulonglong2* r3 = (const ulonglong2*)&relu_s[cur][3][kh * 128];

        u64 a0 = 0, a1 = 0, a2 = 0, a3 = 0;
        #pragma unroll
        for (int i = 0; i < 32; i++) {
            ulonglong2 wv = w[i];
            ulonglong2 v0 = r0[i], v1 = r1[i], v2 = r2[i], v3 = r3[i];
            a0 = ffma2(wv.x, v0.x, a0);
            a1 = ffma2(wv.x, v1.x, a1);
            a2 = ffma2(wv.x, v2.x, a2);
            a3 = ffma2(wv.x, v3.x, a3);
            a0 = ffma2(wv.y, v0.y, a0);
            a1 = ffma2(wv.y, v1.y, a1);
            a2 = ffma2(wv.y, v2.y, a2);
            a3 = ffma2(wv.y, v3.y, a3);
        }
        float2 f0 = unpk(a0), f1 = unpk(a1), f2 = unpk(a2), f3 = unpk(a3);
        float s0 = f0.x + f0.y, s1 = f1.x + f1.y, s2 = f2.x + f2.y, s3 = f3.x + f3.y;

        // own-pair sums / other-pair sums
        float ownX = kh ? s2 : s0;
        float ownY = kh ? s3 : s1;
        float othX = kh ? s0 : s2;
        float othY = kh ? s1 : s3;

        red[kh ^ 1][row] = make_float2(othX, othY);
        __syncthreads();                       // cross-half red exchange

        {
            float2 p = red[kh][row];
            float rcA = ownX + p.x + iA + bh;
            float rcB = ownY + p.y + iB + bh;
            hA = 0.9f * hA + 0.1f * rcA;
            hB = 0.9f * hB + 0.1f * rcB;

            int nxt = cur ^ 1;
            float eA = fmaxf(hA, 0.f), eB = fmaxf(hB, 0.f);

            if (t + 1 < T) {
                unsigned offA = (unsigned)((((nxt * 4 + bb0) * H) + grow) * 4);
                unsigned offB = offA + (unsigned)(H * 4);
                unsigned mbo  = (unsigned)(nxt << 3);
                // publish to own CTA and peer CTA via st.async with
                // transaction tracking (4 B each; 4096 B total per barrier fill)
                ST_ASYNC_B32(own_relu  + offA, eA, own_mb  + mbo);
                ST_ASYNC_B32(own_relu  + offB, eB, own_mb  + mbo);
                ST_ASYNC_B32(peer_relu + offA, eA, peer_mb + mbo);
                ST_ASYNC_B32(peer_relu + offB, eB, peer_mb + mbo);
            }

            // h history for the deferred output GEMM (single-use: streaming store)
            size_t hb = ((size_t)t * B + b0 + bb0) * H + grow;
            __stcs(&g_hh[hb],     hA);
            __stcs(&g_hh[hb + H], hB);

            iA = nA; iB = nB;
        }
    }
}

// =====================================================================
// P3: out[b][t][o] = h_hist[t][b][:] . W_out[o][:] + b_out[o]
// One block per t. thread = (ksec = tid>>5, o = tid&31); 32 rounds of
// 8 batch rows; k-split partials reduced through smem.
// =====================================================================
__global__ void __launch_bounds__(256) out_kernel(const float* __restrict__ Wout,
                                                  const float* __restrict__ bout,
                                                  float* __restrict__ out) {
    int t   = blockIdx.x;
    int tid = threadIdx.x;
    int o   = tid & 31;
    int ks  = tid >> 5;                 // k-section 0..7 (32 k each)

    __shared__ float hs[8][H];          // 8 batch rows  (8 KB)
    __shared__ float red[8][8][O];      // [ksec][bb][o] (8 KB)

    // W_out[o][ks*32 .. +32) in registers (16 f32x2)
    u64 w[16];
    {
        const ulonglong2* wp = (const ulonglong2*)(Wout + (size_t)o * H + ks * 32);
        #pragma unroll
        for (int i = 0; i < 8; i++) { ulonglong2 v = wp[i]; w[2*i] = v.x; w[2*i+1] = v.y; }
    }
    float bo = bout[o];

    const float4* hg = (const float4*)(g_hh + (size_t)t * B * H);
    float4 p0 = __ldcs(&hg[tid]), p1 = __ldcs(&hg[tid + 256]);  // prefetch round 0

    for (int r = 0; r < 32; r++) {
        ((float4*)hs)[tid]       = p0;
        ((float4*)hs)[tid + 256] = p1;
        if (r + 1 < 32) {                        // prefetch next round (streaming)
            p0 = __ldcs(&hg[(r + 1) * 512 + tid]);
            p1 = __ldcs(&hg[(r + 1) * 512 + 256 + tid]);
        }
        __syncthreads();

        #pragma unroll
        for (int bb = 0; bb < 8; bb++) {
            const u64* hp = (const u64*)&hs[bb][ks * 32];
            u64 a0 = 0, a1 = 0;
            #pragma unroll
            for (int i = 0; i < 8; i++) {
                a0 = ffma2(w[2*i],   hp[2*i],   a0);
                a1 = ffma2(w[2*i+1], hp[2*i+1], a1);
            }
            float2 fa = unpk(a0), fb = unpk(a1);
            red[ks][bb][o] = fa.x + fa.y + fb.x + fb.y;
        }
        __syncthreads();

        {   // reduce 8 k-sections; thread -> (bb = tid>>5, o = tid&31)
            int bb = tid >> 5;
            float s = bo;
            #pragma unroll
            for (int k = 0; k < 8; k++) s += red[k][bb][o];
            int b = r * 8 + bb;
            out[((size_t)b * T + t) * O + o] = s;
        }
        __syncthreads();
    }
}

// =====================================================================
extern "C" void kernel_launch(void* const* d_in, const int* in_sizes, int n_in,
                              void* d_out, int out_size) {
    const float* x    = (const float*)d_in[0];
    const float* task = (const float*)d_in[1];
    const float* Win  = (const float*)d_in[2];
    const float* bin  = (const float*)d_in[3];
    const float* Whh  = (const float*)d_in[4];
    const float* bhh  = (const float*)d_in[5];
    const float* Wout = (const float*)d_in[6];
    const float* bout = (const float*)d_in[7];
    float* out = (float*)d_out;

    inproj_kernel<<<dim3(B, T / TT), 256>>>(x, task, Win, bin);
    scan_kernel<<<128, 256>>>(Whh, bhh);
    out_kernel<<<T, 256>>>(Wout, bout, out);
}

// round 12
// speedup vs baseline: 1.2266x; 1.0543x over previous
#include <cuda_runtime.h>
#include <cstdint>

// Problem constants
#define B    256
#define T    2000
#define H    256
#define NIN  64
#define NT   8
#define DIN  72   // NIN + NT
#define O    32

typedef unsigned long long u64;

// ---------- packed f32x2 helpers (sm_100+) ----------
__device__ __forceinline__ u64 ffma2(u64 a, u64 b, u64 c) {
    u64 d;
    asm("fma.rn.f32x2 %0, %1, %2, %3;" : "=l"(d) : "l"(a), "l"(b), "l"(c));
    return d;
}
__device__ __forceinline__ float2 unpk(u64 v) {
    float2 r;
    asm("mov.b64 {%0, %1}, %2;" : "=f"(r.x), "=f"(r.y) : "l"(v));
    return r;
}

// mbarrier try_wait (parity). CLUSTER-scope acquire: half of each buffer's
// transactions are peer-CTA st.async writes.
__device__ __forceinline__ void mbar_wait(unsigned mb, unsigned phase) {
    unsigned done;
    asm volatile(
        "{\n\t.reg .pred p;\n\t"
        "mbarrier.try_wait.parity.acquire.cluster.shared::cta.b64 p, [%1], %2;\n\t"
        "selp.b32 %0, 1, 0, p;\n\t}"
        : "=r"(done) : "r"(mb), "r"(phase) : "memory");
    if (!done) {
        asm volatile(
            "{\n\t.reg .pred P1;\n\t"
            "WL%=:\n\t"
            "mbarrier.try_wait.parity.acquire.cluster.shared::cta.b64 P1, [%0], %1, 0x989680;\n\t"
            "@P1 bra.uni WD%=;\n\t"
            "bra.uni WL%=;\n\t"
            "WD%=:\n\t}"
            :: "r"(mb), "r"(phase) : "memory");
    }
}

#define MBAR_INIT(mb, cnt) \
    asm volatile("mbarrier.init.shared.b64 [%0], %1;" :: "r"(mb), "r"(cnt) : "memory")
#define MBAR_ARM(mb, tx) \
    asm volatile("mbarrier.arrive.expect_tx.shared.b64 _, [%0], %1;" :: "r"(mb), "r"(tx) : "memory")
#define ST_ASYNC_B32(daddr, val, mbaddr) \
    asm volatile("st.async.shared::cluster.mbarrier::complete_tx::bytes.b32 [%0], %1, [%2];" \
                 :: "r"(daddr), "r"(__float_as_uint(val)), "r"(mbaddr) : "memory")

// ---------- scratch (device globals: allocation-free) ----------
__device__ float g_inp[(size_t)T * B * H];             // [t][b][h] 524 MB
__device__ float g_hh [(size_t)T * B * H];             // [t][b][h] 524 MB

// =====================================================================
// P1: input projection (measured 498us; unchanged — don't touch measured
// components while the scan A/B is pending)
// =====================================================================
#define TT 50
__global__ void __launch_bounds__(256, 2) inproj_kernel(const float* __restrict__ x,
                                                        const float* __restrict__ task,
                                                        const float* __restrict__ Win,
                                                        const float* __restrict__ bin) {
    int b  = blockIdx.x;
    int t0 = blockIdx.y * TT;
    int h  = threadIdx.x;

    __shared__ float xs[TT * NIN];
    __shared__ float ts[NT];

    if (h < NT) ts[h] = task[b * NT + h];

    u64 w[32];
    {
        const float4* wr = (const float4*)(Win + (size_t)h * DIN);
        #pragma unroll
        for (int i = 0; i < 16; i++) {
            float4 v = wr[i];
            asm("mov.b64 %0, {%1, %2};" : "=l"(w[2*i])   : "f"(v.x), "f"(v.y));
            asm("mov.b64 %0, {%1, %2};" : "=l"(w[2*i+1]) : "f"(v.z), "f"(v.w));
        }
    }

    {
        const float4* xg = (const float4*)(x + ((size_t)b * T + t0) * NIN);
        float4* xsv = (float4*)xs;
        for (int i = h; i < TT * NIN / 4; i += 256) xsv[i] = xg[i];
    }
    __syncthreads();

    float tp = bin[h];
    #pragma unroll
    for (int j = 0; j < NT; j++) tp = fmaf(Win[h * DIN + NIN + j], ts[j], tp);

    for (int tt = 0; tt < TT; tt += 2) {
        const ulonglong2* xp = (const ulonglong2*)&xs[tt * NIN];
        const ulonglong2* xq = (const ulonglong2*)&xs[(tt + 1) * NIN];
        u64 a0 = 0, a1 = 0, c0 = 0, c1 = 0;
        #pragma unroll
        for (int i = 0; i < 16; i++) {
            ulonglong2 v = xp[i], q = xq[i];
            a0 = ffma2(w[2*i],   v.x, a0);
            a1 = ffma2(w[2*i+1], v.y, a1);
            c0 = ffma2(w[2*i],   q.x, c0);
            c1 = ffma2(w[2*i+1], q.y, c1);
        }
        float2 f0 = unpk(a0), f1 = unpk(a1), g0 = unpk(c0), g1 = unpk(c1);
        __stcs(&g_inp[((size_t)(t0 + tt) * B + b) * H + h],
               f0.x + f0.y + f1.x + f1.y + tp);
        __stcs(&g_inp[((size_t)(t0 + tt + 1) * B + b) * H + h],
               g0.x + g0.y + g1.x + g1.y + tp);
    }
}

// =====================================================================
// P2: the scan — 4-way k-split, 512 threads/CTA (unmeasured; under test).
// 64 clusters x 2 CTAs. Cluster c -> batch rows [4c, 4c+4).
// CTA rank r owns output rows [128r, 128r+128).
// Thread = (row, kq): row = tid&127, kq = tid>>7 (k-quarter, 64 k).
//   - weights: W_hh[grow][kq*64 .. +64) = 16 ulonglong2 = 64 regs
//     (half of the 2-way split -> ptxas headroom to pipeline LDS)
//   - computes partials for ALL 4 batches over its k-quarter
//     (128 FFMA2/thread; 4 warps/SMSP doubles latency cover)
//   - 4-way smem reduction red[kq_src][batch][row] (conflict-free)
//   - owns batch kq for the epilogue: h update, g_hh store, relu publish
// Per-step sync: IDENTICAL to the measured round-10 design — st.async
// publication (1 own-CTA + 1 peer store/thread; 512*2*4B = 4096 B =
// expect_tx per buffer) + try_wait.parity.acquire.cluster.
// =====================================================================
__global__ void __launch_bounds__(512, 1) __cluster_dims__(2, 1, 1)
scan_kernel(const float* __restrict__ Whh, const float* __restrict__ bhh) {
    int tid = threadIdx.x;
    int row = tid & 127;
    int kq  = tid >> 7;                 // k-quarter 0..3; also the owned batch
    unsigned rank;
    asm("mov.u32 %0, %%cluster_ctarank;" : "=r"(rank));
    int b0   = (blockIdx.x >> 1) * 4;
    int grow = (int)rank * 128 + row;   // global output row (== my relu k-index)

    __shared__ float relu_s[2][4][H];   // [buf][batch][k]  8 KB
    __shared__ float red[4][4][128];    // [kq_src][batch][row] 8 KB
    __shared__ __align__(8) u64 mbar_s[2];

    // weight quarter-row in registers: W_hh[grow][kq*64 .. +64)
    ulonglong2 w[16];
    {
        const ulonglong2* wp = (const ulonglong2*)(Whh + (size_t)grow * H + kq * 64);
        #pragma unroll
        for (int i = 0; i < 16; i++) w[i] = wp[i];
    }
    float bh = bhh[grow];

    unsigned mb_local = (unsigned)__cvta_generic_to_shared(&mbar_s[0]);
    unsigned relu_cta = (unsigned)__cvta_generic_to_shared(&relu_s[0][0][0]);

    if (tid == 0) {
        MBAR_INIT(mb_local,     1u);
        MBAR_INIT(mb_local + 8, 1u);
        MBAR_ARM(mb_local,     4096u);   // buffer 0's first async fill (during t=1)
        MBAR_ARM(mb_local + 8, 4096u);   // buffer 1's first fill (during t=0)
    }
    // zero relu buffer 0 (h0 = 0 -> relu = 0)
    for (int i = tid; i < 4 * H; i += 512) ((float*)relu_s[0])[i] = 0.0f;

    // persistent h state + input-proj reg for the ONE owned (batch=kq, row)
    float hS = 0.f;
    float iS = __ldcs(&g_inp[((size_t)b0 + kq) * H + grow]);   // t = 0
    __syncthreads();
    // cluster sync once: mbarrier init visible before any peer st.async
    asm volatile("barrier.cluster.arrive.aligned;" ::: "memory");
    asm volatile("barrier.cluster.wait.aligned;"   ::: "memory");

    unsigned own_relu, peer_relu, own_mb, peer_mb;
    asm("mapa.shared::cluster.u32 %0, %1, %2;" : "=r"(own_relu)  : "r"(relu_cta), "r"(rank));
    asm("mapa.shared::cluster.u32 %0, %1, %2;" : "=r"(peer_relu) : "r"(relu_cta), "r"(rank ^ 1u));
    asm("mapa.shared::cluster.u32 %0, %1, %2;" : "=r"(own_mb)    : "r"(mb_local), "r"(rank));
    asm("mapa.shared::cluster.u32 %0, %1, %2;" : "=r"(peer_mb)   : "r"(mb_local), "r"(rank ^ 1u));

    unsigned phases = 0;   // bit j = parity for mbar[j]'s next wait

    for (int t = 0; t < T; t++) {
        int cur = t & 1;

        // prefetch next step's input projection before the wait
        float nS = 0.f;
        if (t + 1 < T) {
            nS = __ldcs(&g_inp[((size_t)(t + 1) * B + b0 + kq) * H + grow]);
        }

        if (t) {
            unsigned mb = mb_local + (unsigned)(cur << 3);
            mbar_wait(mb, (phases >> cur) & 1u);
            phases ^= (1u << cur);
            if (tid == 0) MBAR_ARM(mb, 4096u);   // re-arm for fill at step t+1
        }

        // 4 batch dot-product partials over k-quarter kq (warp-uniform
        // addresses -> smem broadcast). Two accumulators per batch for ILP.
        const ulonglong2* r0 = (const ulonglong2*)&relu_s[cur][0][kq * 64];
        const ulonglong2* r1 = (const ulonglong2*)&relu_s[cur][1][kq * 64];
        const ulonglong2* r2 = (const ulonglong2*)&relu_s[cur][2][kq * 64];
        const ulonglong2* r3 = (const ulonglong2*)&relu_s[cur][3][kq * 64];

        u64 a0 = 0, a1 = 0, a2 = 0, a3 = 0;
        u64 c0 = 0, c1 = 0, c2 = 0, c3 = 0;
        #pragma unroll
        for (int i = 0; i < 8; i++) {
            ulonglong2 wv = w[i];
            ulonglong2 v0 = r0[i], v1 = r1[i], v2 = r2[i], v3 = r3[i];
            a0 = ffma2(wv.x, v0.x, a0);  a0 = ffma2(wv.y, v0.y, a0);
            a1 = ffma2(wv.x, v1.x, a1);  a1 = ffma2(wv.y, v1.y, a1);
            a2 = ffma2(wv.x, v2.x, a2);  a2 = ffma2(wv.y, v2.y, a2);
            a3 = ffma2(wv.x, v3.x, a3);  a3 = ffma2(wv.y, v3.y, a3);
        }
        #pragma unroll
        for (int i = 8; i < 16; i++) {
            ulonglong2 wv = w[i];
            ulonglong2 v0 = r0[i], v1 = r1[i], v2 = r2[i], v3 = r3[i];
            c0 = ffma2(wv.x, v0.x, c0);  c0 = ffma2(wv.y, v0.y, c0);
            c1 = ffma2(wv.x, v1.x, c1);  c1 = ffma2(wv.y, v1.y, c1);
            c2 = ffma2(wv.x, v2.x, c2);  c2 = ffma2(wv.y, v2.y, c2);
            c3 = ffma2(wv.x, v3.x, c3);  c3 = ffma2(wv.y, v3.y, c3);
        }
        float2 fa0 = unpk(a0), fa1 = unpk(a1), fa2 = unpk(a2), fa3 = unpk(a3);
        float2 fc0 = unpk(c0), fc1 = unpk(c1), fc2 = unpk(c2), fc3 = unpk(c3);
        float p0 = fa0.x + fa0.y + fc0.x + fc0.y;
        float p1 = fa1.x + fa1.y + fc1.x + fc1.y;
        float p2 = fa2.x + fa2.y + fc2.x + fc2.y;
        float p3 = fa3.x + fa3.y + fc3.x + fc3.y;

        red[kq][0][row] = p0;
        red[kq][1][row] = p1;
        red[kq][2][row] = p2;
        red[kq][3][row] = p3;
        __syncthreads();                 // cross-quarter exchange

        {
            // sum the 4 k-quarter partials for the owned batch (= kq)
            float s = red[0][kq][row] + red[1][kq][row]
                    + red[2][kq][row] + red[3][kq][row];
            float rc = s + iS + bh;
            hS = 0.9f * hS + 0.1f * rc;

            // h history (single-use: streaming store)
            __stcs(&g_hh[((size_t)t * B + b0 + kq) * H + grow], hS);

            int nxt = cur ^ 1;
            float e = fmaxf(hS, 0.f);
            if (t + 1 < T) {
                unsigned off = (unsigned)((((nxt * 4 + kq) * H) + grow) * 4);
                unsigned mbo = (unsigned)(nxt << 3);
                ST_ASYNC_B32(own_relu  + off, e, own_mb  + mbo);
                ST_ASYNC_B32(peer_relu + off, e, peer_mb + mbo);
            }
            iS = nS;
        }
    }
}

// =====================================================================
// P3: out[b][t][o] = h_hist[t][b][:] . W_out[o][:] + b_out[o]
// =====================================================================
__global__ void __launch_bounds__(256) out_kernel(const float* __restrict__ Wout,
                                                  const float* __restrict__ bout,
                                                  float* __restrict__ out) {
    int t   = blockIdx.x;
    int tid = threadIdx.x;
    int o   = tid & 31;
    int ks  = tid >> 5;

    __shared__ float hs[8][H];
    __shared__ float red[8][8][O];

    u64 w[16];
    {
        const ulonglong2* wp = (const ulonglong2*)(Wout + (size_t)o * H + ks * 32);
        #pragma unroll
        for (int i = 0; i < 8; i++) { ulonglong2 v = wp[i]; w[2*i] = v.x; w[2*i+1] = v.y; }
    }
    float bo = bout[o];

    const float4* hg = (const float4*)(g_hh + (size_t)t * B * H);
    float4 p0 = __ldcs(&hg[tid]), p1 = __ldcs(&hg[tid + 256]);

    for (int r = 0; r < 32; r++) {
        ((float4*)hs)[tid]       = p0;
        ((float4*)hs)[tid + 256] = p1;
        if (r + 1 < 32) {
            p0 = __ldcs(&hg[(r + 1) * 512 + tid]);
            p1 = __ldcs(&hg[(r + 1) * 512 + 256 + tid]);
        }
        __syncthreads();

        #pragma unroll
        for (int bb = 0; bb < 8; bb++) {
            const u64* hp = (const u64*)&hs[bb][ks * 32];
            u64 a0 = 0, a1 = 0;
            #pragma unroll
            for (int i = 0; i < 8; i++) {
                a0 = ffma2(w[2*i],   hp[2*i],   a0);
                a1 = ffma2(w[2*i+1], hp[2*i+1], a1);
            }
            float2 fa = unpk(a0), fb = unpk(a1);
            red[ks][bb][o] = fa.x + fa.y + fb.x + fb.y;
        }
        __syncthreads();

        {
            int bb = tid >> 5;
            float s = bo;
            #pragma unroll
            for (int k = 0; k < 8; k++) s += red[k][bb][o];
            int b = r * 8 + bb;
            out[((size_t)b * T + t) * O + o] = s;
        }
        __syncthreads();
    }
}

// =====================================================================
extern "C" void kernel_launch(void* const* d_in, const int* in_sizes, int n_in,
                              void* d_out, int out_size) {
    const float* x    = (const float*)d_in[0];
    const float* task = (const float*)d_in[1];
    const float* Win  = (const float*)d_in[2];
    const float* bin  = (const float*)d_in[3];
    const float* Whh  = (const float*)d_in[4];
    const float* bhh  = (const float*)d_in[5];
    const float* Wout = (const float*)d_in[6];
    const float* bout = (const float*)d_in[7];
    float* out = (float*)d_out;

    inproj_kernel<<<dim3(B, T / TT), 256>>>(x, task, Win, bin);
    scan_kernel<<<128, 512>>>(Whh, bhh);
    out_kernel<<<T, 256>>>(Wout, bout, out);
}